// round 12
// baseline (speedup 1.0000x reference)
#include <cuda_runtime.h>
#include <cuda_fp16.h>

#define BATCH   256
#define IN_DIM  1024
#define WIDTH   64000
#define KOUT    10
#define GROUP   (WIDTH / KOUT)   // 6400
#define NS      80               // splits per group
#define JS      (GROUP / NS)     // 80 l3-neurons per block
#define L3WARPS 8
#define JW      (JS / L3WARPS)   // 10 l3-neurons per warp

// x transposed + quantized unorm8: [1024][256] = 256 KB (fits per-SM L1!)
__device__ __align__(256) unsigned char g_xT[IN_DIM * BATCH];
// Per-neuron coefficients pre-broadcast: uint4 = {k0k0,k1k1,k2k2,k3k3}
// layer 0: folded for byte-domain inputs (k1,k2,k3 divided by 255)
__device__ uint4  g_coefh4[3 * WIDTH];                     // 3 MB
__device__ float  g_part[KOUT * NS * BATCH];               // 800 KB

// ---------------------------------------------------------------------------
__device__ __forceinline__ __half2 u2h2(unsigned int u) {
    return *reinterpret_cast<__half2*>(&u);
}
__device__ __forceinline__ __half2 h2const(unsigned short bits) {
    return __half2half2(__ushort_as_half(bits));
}
// Decode 4 unorm8 bytes -> two half2 of byte VALUES [0,255]
__device__ __forceinline__ void decode4(unsigned int v, __half2& lo, __half2& hi) {
    const unsigned int m = 0x64646464u;
    const __half2 h1024 = h2const(0x6400);
    unsigned int t0, t1;
    asm("prmt.b32 %0, %1, %2, 0x4140;" : "=r"(t0) : "r"(v), "r"(m));
    asm("prmt.b32 %0, %1, %2, 0x4342;" : "=r"(t1) : "r"(v), "r"(m));
    lo = __hsub2(u2h2(t0), h1024);
    hi = __hsub2(u2h2(t1), h1024);
}
// plain value-domain gate: k0 + k1*a + k2*b + k3*(a*b)
__device__ __forceinline__ __half2 gate2(__half2 a, __half2 b,
                                         __half2 k0, __half2 k1,
                                         __half2 k2, __half2 k3) {
    __half2 t = __hfma2(k1, a, k0);
    t = __hfma2(k2, b, t);
    return __hfma2(k3, __hmul2(a, b), t);
}
// byte-domain-input gate (a',b' in [0,255], constants pre-folded /255):
// out = k0 + k1*a' + k2*b' + k3*((a'/255)*b')   — value-domain fp16 result
__device__ __forceinline__ __half2 gate2b(__half2 a, __half2 b,
                                          __half2 k0, __half2 k1,
                                          __half2 k2, __half2 k3,
                                          __half2 inv255) {
    __half2 t = __hfma2(k1, a, k0);
    t = __hfma2(k2, b, t);
    __half2 as = __hmul2(a, inv255);
    return __hfma2(k3, __hmul2(as, b), t);
}

// ---------------------------------------------------------------------------
// Prologue: blocks [0,256) transpose+quantize x -> xT u8; rest compute coefs.
__global__ __launch_bounds__(256)
void k_pre(const float* __restrict__ x,
           const float* __restrict__ w1,
           const float* __restrict__ w2,
           const float* __restrict__ w3) {
    if (blockIdx.x < 256) {
        __shared__ float tile[32][33];
        int d0 = (blockIdx.x & 31) * 32;
        int b0 = (blockIdx.x >> 5) * 32;
        int tx = threadIdx.x & 31;
        int ty = threadIdx.x >> 5;
        #pragma unroll
        for (int r = 0; r < 4; r++)
            tile[ty + r * 8][tx] =
                x[(size_t)(b0 + ty + r * 8) * IN_DIM + d0 + tx];
        __syncthreads();
        #pragma unroll
        for (int r = 0; r < 4; r++) {
            float v = tile[tx][ty + r * 8];
            g_xT[(size_t)(d0 + ty + r * 8) * BATCH + b0 + tx] =
                (unsigned char)__float2uint_rn(__saturatef(v) * 255.f);
        }
        return;
    }

    int tid = (blockIdx.x - 256) * blockDim.x + threadIdx.x;
    if (tid >= 3 * WIDTH) return;
    int layer = tid / WIDTH;
    int n     = tid - layer * WIDTH;
    const float* w = (layer == 0) ? w1 : (layer == 1) ? w2 : w3;
    w += (size_t)n * 16;

    float v[16];
    float m = -1e30f;
    #pragma unroll
    for (int i = 0; i < 16; i++) { v[i] = w[i]; m = fmaxf(m, v[i]); }
    float s = 0.f;
    #pragma unroll
    for (int i = 0; i < 16; i++) { v[i] = __expf(v[i] - m); s += v[i]; }
    float inv = __fdividef(1.0f, s);
    #pragma unroll
    for (int i = 0; i < 16; i++) v[i] *= inv;

    float c0 = v[8]+v[9]+v[10]+v[11]+v[12]+v[13]+v[14]+v[15];
    float c1 = v[2]+v[3]+v[6]+v[7] - v[8]-v[9]-v[12]-v[13];
    float c2 = v[4]+v[5]+v[6]+v[7] - v[8]-v[9]-v[10]-v[11];
    float c3 = v[1] - v[2] - v[4] - 2.f*v[6] - v[7]
             + v[8] + 2.f*v[9] + v[11] + v[13] - v[14];

    if (layer == 0) {           // byte-domain folding for l1
        c1 *= (1.f / 255.f);
        c2 *= (1.f / 255.f);
        c3 *= (1.f / 255.f);    // used with one-side prescale a'/255
    }
    __half2 h0 = __half2half2(__float2half_rn(c0));
    __half2 h1 = __half2half2(__float2half_rn(c1));
    __half2 h2 = __half2half2(__float2half_rn(c2));
    __half2 h3 = __half2half2(__float2half_rn(c3));
    uint4 pk;
    pk.x = *reinterpret_cast<unsigned int*>(&h0);
    pk.y = *reinterpret_cast<unsigned int*>(&h1);
    pk.z = *reinterpret_cast<unsigned int*>(&h2);
    pk.w = *reinterpret_cast<unsigned int*>(&h3);
    g_coefh4[tid] = pk;
}

// ---------------------------------------------------------------------------
// Fully fused 3-layer network + group sum. Each l3-neuron recomputed from xT:
//   l3(n) = gate(l2(ia3[n]), l2(ib3[n]));  l2(m) = gate(l1(ia2[m]), l1(ib2[m]))
//   l1(p) = gate(xT[ia1[p]], xT[ib1[p]])
// Warp per l3-neuron chain, lane handles 8 batch elements. All gathers hit
// the 256 KB u8 xT (L1-resident). Intermediates stay in fp16 registers.
__global__ __launch_bounds__(256)
void k_fused(const int* __restrict__ ia1, const int* __restrict__ ib1,
             const int* __restrict__ ia2, const int* __restrict__ ib2,
             const int* __restrict__ ia3, const int* __restrict__ ib3) {
    int k    = blockIdx.x;            // 0..9
    int s    = blockIdx.y;            // 0..NS-1
    int w    = threadIdx.x >> 5;      // 0..7
    int lane = threadIdx.x & 31;

    const unsigned char* src = g_xT;
    const __half2 inv255 = h2const(0x1C04);  // 1/255 ≈ 0.0039216 in fp16
    int n0 = k * GROUP + s * JS + w * JW;

    __half2 acc[4];
    #pragma unroll
    for (int h = 0; h < 4; h++) acc[h] = h2const(0);

    for (int j = 0; j < JW; j++) {
        int n = n0 + j;
        // ---- index chase (warp-uniform scalar loads) ----
        int mA = __ldg(ia3 + n), mB = __ldg(ib3 + n);
        int p0 = __ldg(ia2 + mA), p1 = __ldg(ib2 + mA);
        int p2 = __ldg(ia2 + mB), p3 = __ldg(ib2 + mB);
        int p[4] = {p0, p1, p2, p3};
        int qa[4], qb[4];
        #pragma unroll
        for (int g = 0; g < 4; g++) {
            qa[g] = __ldg(ia1 + p[g]);
            qb[g] = __ldg(ib1 + p[g]);
        }
        // ---- 8 row gathers from xT (uint2 = 8 bytes per lane) ----
        uint2 ra[4], rb[4];
        #pragma unroll
        for (int g = 0; g < 4; g++) {
            ra[g] = __ldg((const uint2*)(src + (size_t)qa[g] * BATCH) + lane);
            rb[g] = __ldg((const uint2*)(src + (size_t)qb[g] * BATCH) + lane);
        }
        // ---- 4 layer-1 gates (byte-domain inputs -> fp16 values) ----
        __half2 l1v[4][4];
        #pragma unroll
        for (int g = 0; g < 4; g++) {
            uint4 pc = __ldg(&g_coefh4[p[g]]);
            __half2 k0 = u2h2(pc.x), k1 = u2h2(pc.y),
                    k2 = u2h2(pc.z), k3 = u2h2(pc.w);
            __half2 aL, aH, a2L, a2H, bL, bH, b2L, b2H;
            decode4(ra[g].x, aL, aH);   decode4(ra[g].y, a2L, a2H);
            decode4(rb[g].x, bL, bH);   decode4(rb[g].y, b2L, b2H);
            l1v[g][0] = gate2b(aL,  bL,  k0, k1, k2, k3, inv255);
            l1v[g][1] = gate2b(aH,  bH,  k0, k1, k2, k3, inv255);
            l1v[g][2] = gate2b(a2L, b2L, k0, k1, k2, k3, inv255);
            l1v[g][3] = gate2b(a2H, b2H, k0, k1, k2, k3, inv255);
        }
        // ---- 2 layer-2 gates ----
        __half2 l2A[4], l2B[4];
        {
            uint4 pc = __ldg(&g_coefh4[WIDTH + mA]);
            __half2 k0 = u2h2(pc.x), k1 = u2h2(pc.y),
                    k2 = u2h2(pc.z), k3 = u2h2(pc.w);
            #pragma unroll
            for (int h = 0; h < 4; h++)
                l2A[h] = gate2(l1v[0][h], l1v[1][h], k0, k1, k2, k3);
        }
        {
            uint4 pc = __ldg(&g_coefh4[WIDTH + mB]);
            __half2 k0 = u2h2(pc.x), k1 = u2h2(pc.y),
                    k2 = u2h2(pc.z), k3 = u2h2(pc.w);
            #pragma unroll
            for (int h = 0; h < 4; h++)
                l2B[h] = gate2(l1v[2][h], l1v[3][h], k0, k1, k2, k3);
        }
        // ---- layer-3 gate + accumulate ----
        {
            uint4 pc = __ldg(&g_coefh4[2 * WIDTH + n]);
            __half2 k0 = u2h2(pc.x), k1 = u2h2(pc.y),
                    k2 = u2h2(pc.z), k3 = u2h2(pc.w);
            #pragma unroll
            for (int h = 0; h < 4; h++)
                acc[h] = __hadd2(acc[h],
                    gate2(l2A[h], l2B[h], k0, k1, k2, k3));
        }
    }

    __shared__ float part[L3WARPS][BATCH];
    #pragma unroll
    for (int h = 0; h < 4; h++) {
        float2 f = __half22float2(acc[h]);
        part[w][lane * 8 + 2 * h]     = f.x;
        part[w][lane * 8 + 2 * h + 1] = f.y;
    }
    __syncthreads();

    int col = threadIdx.x;
    float v = 0.f;
    #pragma unroll
    for (int i = 0; i < L3WARPS; i++) v += part[i][col];
    g_part[(size_t)(k * NS + s) * BATCH + col] = v;
}

// Stage-2: sum NS partials, scale by 1/TAU, write out[b][k]
__global__ void k_freduce(float* __restrict__ out) {
    int k = blockIdx.x;   // 0..9
    int b = threadIdx.x;  // 0..255
    float acc = 0.f;
    #pragma unroll 8
    for (int s = 0; s < NS; s++)
        acc += g_part[(size_t)(k * NS + s) * BATCH + b];
    out[b * KOUT + k] = acc * (1.0f / 30.0f);
}

// ---------------------------------------------------------------------------
extern "C" void kernel_launch(void* const* d_in, const int* in_sizes, int n_in,
                              void* d_out, int out_size) {
    const float* x   = (const float*)d_in[0];
    const float* w1  = (const float*)d_in[1];
    const float* w2  = (const float*)d_in[2];
    const float* w3  = (const float*)d_in[3];
    const int*   ia1 = (const int*)d_in[4];
    const int*   ib1 = (const int*)d_in[5];
    const int*   ia2 = (const int*)d_in[6];
    const int*   ib2 = (const int*)d_in[7];
    const int*   ia3 = (const int*)d_in[8];
    const int*   ib3 = (const int*)d_in[9];
    float* out = (float*)d_out;

    k_pre<<<256 + (3 * WIDTH + 255) / 256, 256>>>(x, w1, w2, w3);
    k_fused<<<dim3(KOUT, NS), 256>>>(ia1, ib1, ia2, ib2, ia3, ib3);
    k_freduce<<<KOUT, BATCH>>>(out);
}

// round 13
// speedup vs baseline: 1.0396x; 1.0396x over previous
#include <cuda_runtime.h>
#include <cuda_fp16.h>

#define BATCH   256
#define IN_DIM  1024
#define WIDTH   64000
#define KOUT    10
#define GROUP   (WIDTH / KOUT)   // 6400
#define NS      80               // splits per group for fused layer3+reduce
#define JS      (GROUP / NS)     // 80 neurons per block
#define L3WARPS 8
#define JW      (JS / L3WARPS)   // 10 neurons per warp (5 pair-iterations)

// fp16 activations (value domain), [neuron][batch] layout, 16B-aligned rows
__device__ __align__(256) __half g_xT[IN_DIM * BATCH];     // 0.5 MB
__device__ __align__(256) __half g_bufA[WIDTH * BATCH];    // 32.8 MB
__device__ __align__(256) __half g_bufB[WIDTH * BATCH];    // 32.8 MB
__device__ float  g_part[KOUT * NS * BATCH];               // 800 KB

// GATE_COEF rows (const, a, b, ab)
__constant__ float4 c_gate[16] = {
    {0.f, 0.f, 0.f, 0.f}, {0.f, 0.f, 0.f, 1.f},
    {0.f, 1.f, 0.f,-1.f}, {0.f, 1.f, 0.f, 0.f},
    {0.f, 0.f, 1.f,-1.f}, {0.f, 0.f, 1.f, 0.f},
    {0.f, 1.f, 1.f,-2.f}, {0.f, 1.f, 1.f,-1.f},
    {1.f,-1.f,-1.f, 1.f}, {1.f,-1.f,-1.f, 2.f},
    {1.f, 0.f,-1.f, 0.f}, {1.f, 0.f,-1.f, 1.f},
    {1.f,-1.f, 0.f, 0.f}, {1.f,-1.f, 0.f, 1.f},
    {1.f, 0.f, 0.f,-1.f}, {1.f, 0.f, 0.f, 0.f}
};

// ---------------------------------------------------------------------------
__device__ __forceinline__ __half2 gate2(__half2 a, __half2 b,
                                         __half2 k0, __half2 k1,
                                         __half2 k2, __half2 k3) {
    __half2 t = __hfma2(k1, a, k0);
    t = __hfma2(k2, b, t);
    return __hfma2(k3, __hmul2(a, b), t);
}

// In-warp coefficients for neurons n0 and n0+1 from raw weights.
// Lane l: neuron n0 + (l>>4), weight index l&15. Width-16 butterfly softmax
// + 4 GATE_COEF dot products, then broadcast both neurons' coefs to all lanes.
__device__ __forceinline__ void warp_coefs(
        const float* __restrict__ w, int n0,
        __half2& k0a, __half2& k1a, __half2& k2a, __half2& k3a,
        __half2& k0b, __half2& k1b, __half2& k2b, __half2& k3b) {
    const unsigned FULL = 0xffffffffu;
    int lane = threadIdx.x & 31;
    int j    = lane & 15;
    float wv = __ldg(w + (size_t)(n0 + (lane >> 4)) * 16 + j);

    float m = wv;
    #pragma unroll
    for (int d = 1; d < 16; d <<= 1)
        m = fmaxf(m, __shfl_xor_sync(FULL, m, d));
    float e = __expf(wv - m);
    float s = e;
    #pragma unroll
    for (int d = 1; d < 16; d <<= 1)
        s += __shfl_xor_sync(FULL, s, d);
    float v = __fdividef(e, s);

    float4 g = c_gate[j];
    float d0 = v * g.x, d1 = v * g.y, d2 = v * g.z, d3 = v * g.w;
    #pragma unroll
    for (int d = 1; d < 16; d <<= 1) {
        d0 += __shfl_xor_sync(FULL, d0, d);
        d1 += __shfl_xor_sync(FULL, d1, d);
        d2 += __shfl_xor_sync(FULL, d2, d);
        d3 += __shfl_xor_sync(FULL, d3, d);
    }
    k0a = __float2half2_rn(__shfl_sync(FULL, d0, 0));
    k1a = __float2half2_rn(__shfl_sync(FULL, d1, 0));
    k2a = __float2half2_rn(__shfl_sync(FULL, d2, 0));
    k3a = __float2half2_rn(__shfl_sync(FULL, d3, 0));
    k0b = __float2half2_rn(__shfl_sync(FULL, d0, 16));
    k1b = __float2half2_rn(__shfl_sync(FULL, d1, 16));
    k2b = __float2half2_rn(__shfl_sync(FULL, d2, 16));
    k3b = __float2half2_rn(__shfl_sync(FULL, d3, 16));
}

__device__ __forceinline__ uint4 gate_u4(uint4 av, uint4 bv,
        __half2 k0, __half2 k1, __half2 k2, __half2 k3) {
    uint4 r;
    ((__half2*)&r)[0] = gate2(((__half2*)&av)[0], ((__half2*)&bv)[0], k0, k1, k2, k3);
    ((__half2*)&r)[1] = gate2(((__half2*)&av)[1], ((__half2*)&bv)[1], k0, k1, k2, k3);
    ((__half2*)&r)[2] = gate2(((__half2*)&av)[2], ((__half2*)&bv)[2], k0, k1, k2, k3);
    ((__half2*)&r)[3] = gate2(((__half2*)&av)[3], ((__half2*)&bv)[3], k0, k1, k2, k3);
    return r;
}

// ---------------------------------------------------------------------------
// Prologue: ONLY the x transpose (256 blocks, ~1 MB traffic)
__global__ __launch_bounds__(256)
void k_pre(const float* __restrict__ x) {
    __shared__ float tile[32][33];
    int d0 = (blockIdx.x & 31) * 32;
    int b0 = (blockIdx.x >> 5) * 32;
    int tx = threadIdx.x & 31;
    int ty = threadIdx.x >> 5;
    #pragma unroll
    for (int r = 0; r < 4; r++)
        tile[ty + r * 8][tx] =
            x[(size_t)(b0 + ty + r * 8) * IN_DIM + d0 + tx];
    __syncthreads();
    #pragma unroll
    for (int r = 0; r < 4; r++)
        g_xT[(size_t)(d0 + ty + r * 8) * BATCH + b0 + tx] =
            __float2half_rn(tile[tx][ty + r * 8]);
}

// ---------------------------------------------------------------------------
// One logic layer, fp16 in/out, TWO neurons per warp, coefs computed in-warp
// from raw weights (softmax under gather latency).
__global__ __launch_bounds__(256)
void k_layer(int srcSel, int dstSel, const float* __restrict__ w,
             const int* __restrict__ ia, const int* __restrict__ ib) {
    int warp = blockIdx.x * 8 + (threadIdx.x >> 5);
    int n0   = warp * 2;
    int n1   = n0 + 1;
    int lane = threadIdx.x & 31;

    const __half* src = (srcSel == 0) ? g_xT : (srcSel == 1) ? g_bufA : g_bufB;
    __half*       dst = (dstSel == 1) ? g_bufA : g_bufB;

    int A0 = __ldg(ia + n0), B0 = __ldg(ib + n0);
    int A1 = __ldg(ia + n1), B1 = __ldg(ib + n1);

    // 4 independent 16B gathers in flight per lane
    uint4 a0 = __ldg((const uint4*)(src + (size_t)A0 * BATCH) + lane);
    uint4 b0 = __ldg((const uint4*)(src + (size_t)B0 * BATCH) + lane);
    uint4 a1 = __ldg((const uint4*)(src + (size_t)A1 * BATCH) + lane);
    uint4 b1 = __ldg((const uint4*)(src + (size_t)B1 * BATCH) + lane);

    // softmax + coef math executes while gathers are in flight
    __half2 k0a, k1a, k2a, k3a, k0b, k1b, k2b, k3b;
    warp_coefs(w, n0, k0a, k1a, k2a, k3a, k0b, k1b, k2b, k3b);

    ((uint4*)(dst + (size_t)n0 * BATCH))[lane] = gate_u4(a0, b0, k0a, k1a, k2a, k3a);
    ((uint4*)(dst + (size_t)n1 * BATCH))[lane] = gate_u4(a1, b1, k0b, k1b, k2b, k3b);
}

// ---------------------------------------------------------------------------
// Fused layer-3 + partial group sum. 8 warps/block, 2 neurons per iteration
// (coefs in-warp), half2 accumulation, smem cross-warp reduce.
__global__ __launch_bounds__(256)
void k_layer3_reduce(const float* __restrict__ w3,
                     const int* __restrict__ ia, const int* __restrict__ ib) {
    int k    = blockIdx.x;            // 0..9
    int s    = blockIdx.y;            // 0..NS-1
    int w    = threadIdx.x >> 5;      // 0..7
    int lane = threadIdx.x & 31;

    const __half* src = g_bufB;       // layer-2 output
    int nbase = k * GROUP + s * JS + w * JW;

    __half2 acc[4];
    #pragma unroll
    for (int h = 0; h < 4; h++) acc[h] = __half2half2(__ushort_as_half(0));

    #pragma unroll
    for (int jj = 0; jj < JW / 2; jj++) {
        int n0 = nbase + 2 * jj;
        int n1 = n0 + 1;
        int A0 = __ldg(ia + n0), B0 = __ldg(ib + n0);
        int A1 = __ldg(ia + n1), B1 = __ldg(ib + n1);

        uint4 a0 = __ldg((const uint4*)(src + (size_t)A0 * BATCH) + lane);
        uint4 b0 = __ldg((const uint4*)(src + (size_t)B0 * BATCH) + lane);
        uint4 a1 = __ldg((const uint4*)(src + (size_t)A1 * BATCH) + lane);
        uint4 b1 = __ldg((const uint4*)(src + (size_t)B1 * BATCH) + lane);

        __half2 k0a, k1a, k2a, k3a, k0b, k1b, k2b, k3b;
        warp_coefs(w3, n0, k0a, k1a, k2a, k3a, k0b, k1b, k2b, k3b);

        #pragma unroll
        for (int h = 0; h < 4; h++) {
            acc[h] = __hadd2(acc[h],
                gate2(((__half2*)&a0)[h], ((__half2*)&b0)[h], k0a, k1a, k2a, k3a));
            acc[h] = __hadd2(acc[h],
                gate2(((__half2*)&a1)[h], ((__half2*)&b1)[h], k0b, k1b, k2b, k3b));
        }
    }

    __shared__ float part[L3WARPS][BATCH];
    #pragma unroll
    for (int h = 0; h < 4; h++) {
        float2 f = __half22float2(acc[h]);
        part[w][lane * 8 + 2 * h]     = f.x;
        part[w][lane * 8 + 2 * h + 1] = f.y;
    }
    __syncthreads();

    int col = threadIdx.x;
    float v = 0.f;
    #pragma unroll
    for (int i = 0; i < L3WARPS; i++) v += part[i][col];
    g_part[(size_t)(k * NS + s) * BATCH + col] = v;
}

// Stage-2: sum NS partials, scale by 1/TAU, write out[b][k]
__global__ void k_freduce(float* __restrict__ out) {
    int k = blockIdx.x;   // 0..9
    int b = threadIdx.x;  // 0..255
    float acc = 0.f;
    #pragma unroll 8
    for (int s = 0; s < NS; s++)
        acc += g_part[(size_t)(k * NS + s) * BATCH + b];
    out[b * KOUT + k] = acc * (1.0f / 30.0f);
}

// ---------------------------------------------------------------------------
extern "C" void kernel_launch(void* const* d_in, const int* in_sizes, int n_in,
                              void* d_out, int out_size) {
    const float* x   = (const float*)d_in[0];
    const float* w1  = (const float*)d_in[1];
    const float* w2  = (const float*)d_in[2];
    const float* w3  = (const float*)d_in[3];
    const int*   ia1 = (const int*)d_in[4];
    const int*   ib1 = (const int*)d_in[5];
    const int*   ia2 = (const int*)d_in[6];
    const int*   ib2 = (const int*)d_in[7];
    const int*   ia3 = (const int*)d_in[8];
    const int*   ib3 = (const int*)d_in[9];
    float* out = (float*)d_out;

    k_pre<<<256, 256>>>(x);

    k_layer<<<WIDTH / 16, 256>>>(0, 1, w1, ia1, ib1);  // xT   -> bufA
    k_layer<<<WIDTH / 16, 256>>>(1, 2, w2, ia2, ib2);  // bufA -> bufB

    k_layer3_reduce<<<dim3(KOUT, NS), 256>>>(w3, ia3, ib3);
    k_freduce<<<KOUT, BATCH>>>(out);
}

// round 14
// speedup vs baseline: 1.3559x; 1.3043x over previous
#include <cuda_runtime.h>
#include <cuda_fp16.h>

#define BATCH   256
#define IN_DIM  1024
#define WIDTH   64000
#define KOUT    10
#define GROUP   (WIDTH / KOUT)   // 6400
#define NS      80               // splits per group for fused layer3+reduce
#define JS      (GROUP / NS)     // 80 neurons per block
#define L3WARPS 8
#define JW      (JS / L3WARPS)   // 10 neurons per warp
#define CBLK    250              // coef blocks per layer (64000/256)

// fp16 activations (value domain), [neuron][batch] layout, 16B-aligned rows
__device__ __align__(256) __half g_xT[IN_DIM * BATCH];     // 0.5 MB
__device__ __align__(256) __half g_bufA[WIDTH * BATCH];    // 32.8 MB
__device__ __align__(256) __half g_bufB[WIDTH * BATCH];    // 32.8 MB
// Per-neuron coefficients pre-broadcast: uint4 = {k0k0,k1k1,k2k2,k3k3}
__device__ uint4  g_coefh4[3 * WIDTH];                     // 3 MB
__device__ float  g_part[KOUT * NS * BATCH];               // 800 KB

// ---------------------------------------------------------------------------
__device__ __forceinline__ __half2 u2h2(unsigned int u) {
    return *reinterpret_cast<__half2*>(&u);
}
__device__ __forceinline__ __half2 gate2(__half2 a, __half2 b,
                                         __half2 k0, __half2 k1,
                                         __half2 k2, __half2 k3) {
    __half2 t = __hfma2(k1, a, k0);
    t = __hfma2(k2, b, t);
    return __hfma2(k3, __hmul2(a, b), t);
}
__device__ __forceinline__ uint4 gate_u4(uint4 pc, uint4 av, uint4 bv) {
    __half2 k0 = u2h2(pc.x), k1 = u2h2(pc.y), k2 = u2h2(pc.z), k3 = u2h2(pc.w);
    uint4 r;
    ((__half2*)&r)[0] = gate2(((__half2*)&av)[0], ((__half2*)&bv)[0], k0, k1, k2, k3);
    ((__half2*)&r)[1] = gate2(((__half2*)&av)[1], ((__half2*)&bv)[1], k0, k1, k2, k3);
    ((__half2*)&r)[2] = gate2(((__half2*)&av)[2], ((__half2*)&bv)[2], k0, k1, k2, k3);
    ((__half2*)&r)[3] = gate2(((__half2*)&av)[3], ((__half2*)&bv)[3], k0, k1, k2, k3);
    return r;
}

// ---------------------------------------------------------------------------
// Coef block: 256 neurons. Coalesced float4 global loads staged through smem
// (transposed, conflict-free), then per-thread softmax + GATE_COEF fold.
// Must be called by ALL 256 threads of the block (contains __syncthreads).
__device__ __forceinline__ void coef_block(const float* __restrict__ w,
                                           int dstOff, int blk) {
    __shared__ float sw[16][257];
    int n0 = blk * 256;
    const float4* wv = (const float4*)(w + (size_t)n0 * 16);
    #pragma unroll
    for (int it = 0; it < 4; it++) {
        int i = threadIdx.x + it * 256;          // 0..1023
        float4 f = __ldg(wv + i);
        int n = i >> 2;
        int j = (i & 3) * 4;
        sw[j + 0][n] = f.x;
        sw[j + 1][n] = f.y;
        sw[j + 2][n] = f.z;
        sw[j + 3][n] = f.w;
    }
    __syncthreads();

    int t = threadIdx.x;
    float v[16];
    float m = -1e30f;
    #pragma unroll
    for (int i = 0; i < 16; i++) { v[i] = sw[i][t]; m = fmaxf(m, v[i]); }
    float s = 0.f;
    #pragma unroll
    for (int i = 0; i < 16; i++) { v[i] = __expf(v[i] - m); s += v[i]; }
    float inv = __fdividef(1.0f, s);
    #pragma unroll
    for (int i = 0; i < 16; i++) v[i] *= inv;

    float c0 = v[8]+v[9]+v[10]+v[11]+v[12]+v[13]+v[14]+v[15];
    float c1 = v[2]+v[3]+v[6]+v[7] - v[8]-v[9]-v[12]-v[13];
    float c2 = v[4]+v[5]+v[6]+v[7] - v[8]-v[9]-v[10]-v[11];
    float c3 = v[1] - v[2] - v[4] - 2.f*v[6] - v[7]
             + v[8] + 2.f*v[9] + v[11] + v[13] - v[14];

    __half2 h0 = __half2half2(__float2half_rn(c0));
    __half2 h1 = __half2half2(__float2half_rn(c1));
    __half2 h2 = __half2half2(__float2half_rn(c2));
    __half2 h3 = __half2half2(__float2half_rn(c3));
    uint4 pk;
    pk.x = *reinterpret_cast<unsigned int*>(&h0);
    pk.y = *reinterpret_cast<unsigned int*>(&h1);
    pk.z = *reinterpret_cast<unsigned int*>(&h2);
    pk.w = *reinterpret_cast<unsigned int*>(&h3);
    g_coefh4[dstOff + n0 + t] = pk;
}

// ---------------------------------------------------------------------------
// Prologue: blocks [0,256) transpose x -> xT fp16; blocks [256,256+CBLK)
// compute LAYER-1 coefs only (layers 2/3 co-scheduled with layer kernels).
__global__ __launch_bounds__(256)
void k_pre(const float* __restrict__ x, const float* __restrict__ w1) {
    if (blockIdx.x >= 256) {
        coef_block(w1, 0, blockIdx.x - 256);
        return;
    }
    __shared__ float tile[32][33];
    int d0 = (blockIdx.x & 31) * 32;
    int b0 = (blockIdx.x >> 5) * 32;
    int tx = threadIdx.x & 31;
    int ty = threadIdx.x >> 5;
    #pragma unroll
    for (int r = 0; r < 4; r++)
        tile[ty + r * 8][tx] =
            x[(size_t)(b0 + ty + r * 8) * IN_DIM + d0 + tx];
    __syncthreads();
    #pragma unroll
    for (int r = 0; r < 4; r++)
        g_xT[(size_t)(d0 + ty + r * 8) * BATCH + b0 + tx] =
            __float2half_rn(tile[tx][ty + r * 8]);
}

// ---------------------------------------------------------------------------
// One logic layer, fp16 in/out, TWO neurons per warp. Grid is WIDTH/16 layer
// blocks + CBLK coef blocks that compute the NEXT layer's coefficients
// concurrently (filling idle issue slots of the latency-bound layer warps).
__global__ __launch_bounds__(256)
void k_layer(int srcSel, int dstSel, int coefOff,
             const int* __restrict__ ia, const int* __restrict__ ib,
             const float* __restrict__ wnext, int nextOff) {
    if (blockIdx.x >= WIDTH / 16) {
        coef_block(wnext, nextOff, blockIdx.x - WIDTH / 16);
        return;
    }
    int warp = blockIdx.x * 8 + (threadIdx.x >> 5);
    int n0   = warp * 2;
    int n1   = n0 + 1;
    int lane = threadIdx.x & 31;

    const __half* src = (srcSel == 0) ? g_xT : (srcSel == 1) ? g_bufA : g_bufB;
    __half*       dst = (dstSel == 1) ? g_bufA : g_bufB;

    int A0 = __ldg(ia + n0), B0 = __ldg(ib + n0);
    int A1 = __ldg(ia + n1), B1 = __ldg(ib + n1);
    uint4 pc0 = __ldg(&g_coefh4[coefOff + n0]);
    uint4 pc1 = __ldg(&g_coefh4[coefOff + n1]);

    // 4 independent 16B gathers in flight per lane
    uint4 a0 = __ldg((const uint4*)(src + (size_t)A0 * BATCH) + lane);
    uint4 b0 = __ldg((const uint4*)(src + (size_t)B0 * BATCH) + lane);
    uint4 a1 = __ldg((const uint4*)(src + (size_t)A1 * BATCH) + lane);
    uint4 b1 = __ldg((const uint4*)(src + (size_t)B1 * BATCH) + lane);

    ((uint4*)(dst + (size_t)n0 * BATCH))[lane] = gate_u4(pc0, a0, b0);
    ((uint4*)(dst + (size_t)n1 * BATCH))[lane] = gate_u4(pc1, a1, b1);
}

// ---------------------------------------------------------------------------
// Fused layer-3 + partial group sum. 8 warps/block, JW=10 neurons per warp.
// Gates accumulated in half2 (sum <= 10, safe), one cvt to fp32 at the end.
__global__ __launch_bounds__(256)
void k_layer3_reduce(const int* __restrict__ ia, const int* __restrict__ ib) {
    int k    = blockIdx.x;            // 0..9
    int s    = blockIdx.y;            // 0..NS-1
    int w    = threadIdx.x >> 5;      // 0..7
    int lane = threadIdx.x & 31;

    const __half* src = g_bufB;       // layer-2 output
    int n0 = k * GROUP + s * JS + w * JW;

    __half2 acc[4];
    #pragma unroll
    for (int h = 0; h < 4; h++) acc[h] = __half2half2(__ushort_as_half(0));

    #pragma unroll 2
    for (int j = 0; j < JW; j++) {
        int n = n0 + j;
        int A = __ldg(ia + n);
        int B = __ldg(ib + n);
        uint4 pc = __ldg(&g_coefh4[2 * WIDTH + n]);
        uint4 av = __ldg((const uint4*)(src + (size_t)A * BATCH) + lane);
        uint4 bv = __ldg((const uint4*)(src + (size_t)B * BATCH) + lane);

        __half2 k0 = u2h2(pc.x), k1 = u2h2(pc.y), k2 = u2h2(pc.z), k3 = u2h2(pc.w);
        #pragma unroll
        for (int h = 0; h < 4; h++) {
            acc[h] = __hadd2(acc[h],
                gate2(((__half2*)&av)[h], ((__half2*)&bv)[h], k0, k1, k2, k3));
        }
    }

    __shared__ float part[L3WARPS][BATCH];
    #pragma unroll
    for (int h = 0; h < 4; h++) {
        float2 f = __half22float2(acc[h]);
        part[w][lane * 8 + 2 * h]     = f.x;
        part[w][lane * 8 + 2 * h + 1] = f.y;
    }
    __syncthreads();

    int col = threadIdx.x;
    float v = 0.f;
    #pragma unroll
    for (int i = 0; i < L3WARPS; i++) v += part[i][col];
    g_part[(size_t)(k * NS + s) * BATCH + col] = v;
}

// Stage-2: sum NS partials, scale by 1/TAU, write out[b][k]
__global__ void k_freduce(float* __restrict__ out) {
    int k = blockIdx.x;   // 0..9
    int b = threadIdx.x;  // 0..255
    float acc = 0.f;
    #pragma unroll 8
    for (int s = 0; s < NS; s++)
        acc += g_part[(size_t)(k * NS + s) * BATCH + b];
    out[b * KOUT + k] = acc * (1.0f / 30.0f);
}

// ---------------------------------------------------------------------------
extern "C" void kernel_launch(void* const* d_in, const int* in_sizes, int n_in,
                              void* d_out, int out_size) {
    const float* x   = (const float*)d_in[0];
    const float* w1  = (const float*)d_in[1];
    const float* w2  = (const float*)d_in[2];
    const float* w3  = (const float*)d_in[3];
    const int*   ia1 = (const int*)d_in[4];
    const int*   ib1 = (const int*)d_in[5];
    const int*   ia2 = (const int*)d_in[6];
    const int*   ib2 = (const int*)d_in[7];
    const int*   ia3 = (const int*)d_in[8];
    const int*   ib3 = (const int*)d_in[9];
    float* out = (float*)d_out;

    // transpose + layer-1 coefs
    k_pre<<<256 + CBLK, 256>>>(x, w1);
    // layer 1 (+ layer-2 coefs co-scheduled)
    k_layer<<<WIDTH / 16 + CBLK, 256>>>(0, 1, 0,     ia1, ib1, w2, WIDTH);
    // layer 2 (+ layer-3 coefs co-scheduled)
    k_layer<<<WIDTH / 16 + CBLK, 256>>>(1, 2, WIDTH, ia2, ib2, w3, 2 * WIDTH);

    k_layer3_reduce<<<dim3(KOUT, NS), 256>>>(ia3, ib3);
    k_freduce<<<KOUT, BATCH>>>(out);
}

// round 16
// speedup vs baseline: 1.3816x; 1.0189x over previous
#include <cuda_runtime.h>
#include <cuda_fp16.h>

#define BATCH   256
#define IN_DIM  1024
#define WIDTH   64000
#define KOUT    10
#define GROUP   (WIDTH / KOUT)   // 6400
#define NS      80               // splits per group for fused l2+l3+reduce
#define JS      (GROUP / NS)     // 80 l3-neurons per block
#define L3WARPS 8
#define JW      (JS / L3WARPS)   // 10 l3-neurons per warp (5 chunks of 2)
#define CBLK    250              // coef blocks per layer (64000/256)

// fp16 activations (value domain), [neuron][batch] layout, 16B-aligned rows
__device__ __align__(256) __half g_xT[IN_DIM * BATCH];     // 0.5 MB
__device__ __align__(256) __half g_bufA[WIDTH * BATCH];    // 32.8 MB (layer-1 out)
// Per-neuron coefficients pre-broadcast: uint4 = {k0k0,k1k1,k2k2,k3k3}
__device__ uint4  g_coefh4[3 * WIDTH];                     // 3 MB
__device__ float  g_part[KOUT * NS * BATCH];               // 800 KB

// ---------------------------------------------------------------------------
__device__ __forceinline__ __half2 u2h2(unsigned int u) {
    return *reinterpret_cast<__half2*>(&u);
}
__device__ __forceinline__ __half2 gate2(__half2 a, __half2 b,
                                         __half2 k0, __half2 k1,
                                         __half2 k2, __half2 k3) {
    __half2 t = __hfma2(k1, a, k0);
    t = __hfma2(k2, b, t);
    return __hfma2(k3, __hmul2(a, b), t);
}
__device__ __forceinline__ uint4 gate_u4(uint4 pc, uint4 av, uint4 bv) {
    __half2 k0 = u2h2(pc.x), k1 = u2h2(pc.y), k2 = u2h2(pc.z), k3 = u2h2(pc.w);
    uint4 r;
    ((__half2*)&r)[0] = gate2(((__half2*)&av)[0], ((__half2*)&bv)[0], k0, k1, k2, k3);
    ((__half2*)&r)[1] = gate2(((__half2*)&av)[1], ((__half2*)&bv)[1], k0, k1, k2, k3);
    ((__half2*)&r)[2] = gate2(((__half2*)&av)[2], ((__half2*)&bv)[2], k0, k1, k2, k3);
    ((__half2*)&r)[3] = gate2(((__half2*)&av)[3], ((__half2*)&bv)[3], k0, k1, k2, k3);
    return r;
}

// ---------------------------------------------------------------------------
// Coef block: 256 neurons, coalesced float4 loads staged through smem.
__device__ __forceinline__ void coef_block(const float* __restrict__ w,
                                           int dstOff, int blk) {
    __shared__ float sw[16][257];
    int n0 = blk * 256;
    const float4* wv = (const float4*)(w + (size_t)n0 * 16);
    #pragma unroll
    for (int it = 0; it < 4; it++) {
        int i = threadIdx.x + it * 256;          // 0..1023
        float4 f = __ldg(wv + i);
        int n = i >> 2;
        int j = (i & 3) * 4;
        sw[j + 0][n] = f.x;
        sw[j + 1][n] = f.y;
        sw[j + 2][n] = f.z;
        sw[j + 3][n] = f.w;
    }
    __syncthreads();

    int t = threadIdx.x;
    float v[16];
    float m = -1e30f;
    #pragma unroll
    for (int i = 0; i < 16; i++) { v[i] = sw[i][t]; m = fmaxf(m, v[i]); }
    float s = 0.f;
    #pragma unroll
    for (int i = 0; i < 16; i++) { v[i] = __expf(v[i] - m); s += v[i]; }
    float inv = __fdividef(1.0f, s);
    #pragma unroll
    for (int i = 0; i < 16; i++) v[i] *= inv;

    float c0 = v[8]+v[9]+v[10]+v[11]+v[12]+v[13]+v[14]+v[15];
    float c1 = v[2]+v[3]+v[6]+v[7] - v[8]-v[9]-v[12]-v[13];
    float c2 = v[4]+v[5]+v[6]+v[7] - v[8]-v[9]-v[10]-v[11];
    float c3 = v[1] - v[2] - v[4] - 2.f*v[6] - v[7]
             + v[8] + 2.f*v[9] + v[11] + v[13] - v[14];

    __half2 h0 = __half2half2(__float2half_rn(c0));
    __half2 h1 = __half2half2(__float2half_rn(c1));
    __half2 h2 = __half2half2(__float2half_rn(c2));
    __half2 h3 = __half2half2(__float2half_rn(c3));
    uint4 pk;
    pk.x = *reinterpret_cast<unsigned int*>(&h0);
    pk.y = *reinterpret_cast<unsigned int*>(&h1);
    pk.z = *reinterpret_cast<unsigned int*>(&h2);
    pk.w = *reinterpret_cast<unsigned int*>(&h3);
    g_coefh4[dstOff + n0 + t] = pk;
}

// ---------------------------------------------------------------------------
// Prologue: blocks [0,256) transpose x -> xT fp16; then CBLK layer-1 coef
// blocks; then CBLK layer-2 coef blocks.
__global__ __launch_bounds__(256)
void k_pre(const float* __restrict__ x,
           const float* __restrict__ w1, const float* __restrict__ w2) {
    if (blockIdx.x >= 256) {
        int blk = blockIdx.x - 256;
        if (blk < CBLK) coef_block(w1, 0, blk);
        else            coef_block(w2, WIDTH, blk - CBLK);
        return;
    }
    __shared__ float tile[32][33];
    int d0 = (blockIdx.x & 31) * 32;
    int b0 = (blockIdx.x >> 5) * 32;
    int tx = threadIdx.x & 31;
    int ty = threadIdx.x >> 5;
    #pragma unroll
    for (int r = 0; r < 4; r++)
        tile[ty + r * 8][tx] =
            x[(size_t)(b0 + ty + r * 8) * IN_DIM + d0 + tx];
    __syncthreads();
    #pragma unroll
    for (int r = 0; r < 4; r++)
        g_xT[(size_t)(d0 + ty + r * 8) * BATCH + b0 + tx] =
            __float2half_rn(tile[tx][ty + r * 8]);
}

// ---------------------------------------------------------------------------
// Layer 1 only: xT -> bufA, TWO neurons per warp; co-schedules the CBLK
// layer-3 coef blocks (fills idle issue slots of latency-bound layer warps).
__global__ __launch_bounds__(256)
void k_layer1(const int* __restrict__ ia, const int* __restrict__ ib,
              const float* __restrict__ w3) {
    if (blockIdx.x >= WIDTH / 16) {
        coef_block(w3, 2 * WIDTH, blockIdx.x - WIDTH / 16);
        return;
    }
    int warp = blockIdx.x * 8 + (threadIdx.x >> 5);
    int n0   = warp * 2;
    int n1   = n0 + 1;
    int lane = threadIdx.x & 31;

    const __half* src = g_xT;
    __half*       dst = g_bufA;

    int A0 = __ldg(ia + n0), B0 = __ldg(ib + n0);
    int A1 = __ldg(ia + n1), B1 = __ldg(ib + n1);
    uint4 pc0 = __ldg(&g_coefh4[n0]);
    uint4 pc1 = __ldg(&g_coefh4[n1]);

    uint4 a0 = __ldg((const uint4*)(src + (size_t)A0 * BATCH) + lane);
    uint4 b0 = __ldg((const uint4*)(src + (size_t)B0 * BATCH) + lane);
    uint4 a1 = __ldg((const uint4*)(src + (size_t)A1 * BATCH) + lane);
    uint4 b1 = __ldg((const uint4*)(src + (size_t)B1 * BATCH) + lane);

    ((uint4*)(dst + (size_t)n0 * BATCH))[lane] = gate_u4(pc0, a0, b0);
    ((uint4*)(dst + (size_t)n1 * BATCH))[lane] = gate_u4(pc1, a1, b1);
}

// ---------------------------------------------------------------------------
// Fused layer-2 + layer-3 + partial group sum. Chunks of 2 l3-neurons:
// batched warp-uniform index chase (ia3 -> ia2), then 8 independent uint4
// gathers from bufA, 4 inline l2 gates, 2 l3 gates, half2 accumulation.
__global__ __launch_bounds__(256)
void k_l23_reduce(const int* __restrict__ ia2, const int* __restrict__ ib2,
                  const int* __restrict__ ia3, const int* __restrict__ ib3) {
    int k    = blockIdx.x;            // 0..9
    int s    = blockIdx.y;            // 0..NS-1
    int w    = threadIdx.x >> 5;      // 0..7
    int lane = threadIdx.x & 31;

    const __half* src = g_bufA;       // layer-1 output
    int n0 = k * GROUP + s * JS + w * JW;

    __half2 acc[4];
    #pragma unroll
    for (int h = 0; h < 4; h++) acc[h] = __half2half2(__ushort_as_half(0));

    #pragma unroll 2
    for (int jj = 0; jj < JW / 2; jj++) {
        int nA = n0 + 2 * jj;
        int nB = nA + 1;
        // level-1 chase: l2-neuron ids (warp-uniform)
        int m0 = __ldg(ia3 + nA), m1 = __ldg(ib3 + nA);
        int m2 = __ldg(ia3 + nB), m3 = __ldg(ib3 + nB);
        // l3 coefs can load now too (independent of chase level 2)
        uint4 cnA = __ldg(&g_coefh4[2 * WIDTH + nA]);
        uint4 cnB = __ldg(&g_coefh4[2 * WIDTH + nB]);
        // level-2 chase: 8 independent l1-neuron ids + 4 l2 coefs
        int p0 = __ldg(ia2 + m0), p1 = __ldg(ib2 + m0);
        int p2 = __ldg(ia2 + m1), p3 = __ldg(ib2 + m1);
        int p4 = __ldg(ia2 + m2), p5 = __ldg(ib2 + m2);
        int p6 = __ldg(ia2 + m3), p7 = __ldg(ib2 + m3);
        uint4 cm0 = __ldg(&g_coefh4[WIDTH + m0]);
        uint4 cm1 = __ldg(&g_coefh4[WIDTH + m1]);
        uint4 cm2 = __ldg(&g_coefh4[WIDTH + m2]);
        uint4 cm3 = __ldg(&g_coefh4[WIDTH + m3]);
        // 8 independent row gathers (16B per lane)
        uint4 g0 = __ldg((const uint4*)(src + (size_t)p0 * BATCH) + lane);
        uint4 g1 = __ldg((const uint4*)(src + (size_t)p1 * BATCH) + lane);
        uint4 g2 = __ldg((const uint4*)(src + (size_t)p2 * BATCH) + lane);
        uint4 g3 = __ldg((const uint4*)(src + (size_t)p3 * BATCH) + lane);
        uint4 g4 = __ldg((const uint4*)(src + (size_t)p4 * BATCH) + lane);
        uint4 g5 = __ldg((const uint4*)(src + (size_t)p5 * BATCH) + lane);
        uint4 g6 = __ldg((const uint4*)(src + (size_t)p6 * BATCH) + lane);
        uint4 g7 = __ldg((const uint4*)(src + (size_t)p7 * BATCH) + lane);

        // inline layer-2 gates
        uint4 l2a = gate_u4(cm0, g0, g1);   // l2(mA of nA)
        uint4 l2b = gate_u4(cm1, g2, g3);   // l2(mB of nA)
        uint4 l2c = gate_u4(cm2, g4, g5);   // l2(mA of nB)
        uint4 l2d = gate_u4(cm3, g6, g7);   // l2(mB of nB)

        // layer-3 gates + accumulate
        __half2 kA0 = u2h2(cnA.x), kA1 = u2h2(cnA.y),
                kA2 = u2h2(cnA.z), kA3 = u2h2(cnA.w);
        __half2 kB0 = u2h2(cnB.x), kB1 = u2h2(cnB.y),
                kB2 = u2h2(cnB.z), kB3 = u2h2(cnB.w);
        #pragma unroll
        for (int h = 0; h < 4; h++) {
            acc[h] = __hadd2(acc[h],
                gate2(((__half2*)&l2a)[h], ((__half2*)&l2b)[h], kA0, kA1, kA2, kA3));
            acc[h] = __hadd2(acc[h],
                gate2(((__half2*)&l2c)[h], ((__half2*)&l2d)[h], kB0, kB1, kB2, kB3));
        }
    }

    __shared__ float part[L3WARPS][BATCH];
    #pragma unroll
    for (int h = 0; h < 4; h++) {
        float2 f = __half22float2(acc[h]);
        part[w][lane * 8 + 2 * h]     = f.x;
        part[w][lane * 8 + 2 * h + 1] = f.y;
    }
    __syncthreads();

    int col = threadIdx.x;
    float v = 0.f;
    #pragma unroll
    for (int i = 0; i < L3WARPS; i++) v += part[i][col];
    g_part[(size_t)(k * NS + s) * BATCH + col] = v;
}

// Stage-2: sum NS partials, scale by 1/TAU, write out[b][k]
__global__ void k_freduce(float* __restrict__ out) {
    int k = blockIdx.x;   // 0..9
    int b = threadIdx.x;  // 0..255
    float acc = 0.f;
    #pragma unroll 8
    for (int s = 0; s < NS; s++)
        acc += g_part[(size_t)(k * NS + s) * BATCH + b];
    out[b * KOUT + k] = acc * (1.0f / 30.0f);
}

// ---------------------------------------------------------------------------
extern "C" void kernel_launch(void* const* d_in, const int* in_sizes, int n_in,
                              void* d_out, int out_size) {
    const float* x   = (const float*)d_in[0];
    const float* w1  = (const float*)d_in[1];
    const float* w2  = (const float*)d_in[2];
    const float* w3  = (const float*)d_in[3];
    const int*   ia1 = (const int*)d_in[4];
    const int*   ib1 = (const int*)d_in[5];
    const int*   ia2 = (const int*)d_in[6];
    const int*   ib2 = (const int*)d_in[7];
    const int*   ia3 = (const int*)d_in[8];
    const int*   ib3 = (const int*)d_in[9];
    float* out = (float*)d_out;

    // transpose + layer-1 + layer-2 coefs
    k_pre<<<256 + 2 * CBLK, 256>>>(x, w1, w2);
    // layer 1 (+ layer-3 coefs co-scheduled)
    k_layer1<<<WIDTH / 16 + CBLK, 256>>>(ia1, ib1, w3);
    // fused layer-2 + layer-3 + reduce
    k_l23_reduce<<<dim3(KOUT, NS), 256>>>(ia2, ib2, ia3, ib3);
    k_freduce<<<KOUT, BATCH>>>(out);
}

// round 17
// speedup vs baseline: 1.4396x; 1.0420x over previous
#include <cuda_runtime.h>
#include <cuda_fp16.h>

#define BATCH   256
#define IN_DIM  1024
#define WIDTH   64000
#define KOUT    10
#define GROUP   (WIDTH / KOUT)   // 6400
#define NS      80               // splits per group for fused l2+l3+reduce
#define JS      (GROUP / NS)     // 80 l3-neurons per block
#define L3WARPS 8
#define JW      (JS / L3WARPS)   // 10 l3-neurons per warp (5 chunks of 2)
#define CBLK    250              // coef blocks per layer (64000/256)
#define FS      8                // freduce stage-A splits (NS/FS = 10 each)

// fp16 activations (value domain), [neuron][batch] layout, 16B-aligned rows
__device__ __align__(256) __half g_xT[IN_DIM * BATCH];     // 0.5 MB
__device__ __align__(256) __half g_bufA[WIDTH * BATCH];    // 32.8 MB (layer-1 out)
// Per-neuron coefficients pre-broadcast: uint4 = {k0k0,k1k1,k2k2,k3k3}
__device__ uint4  g_coefh4[3 * WIDTH];                     // 3 MB
__device__ float  g_part[KOUT * NS * BATCH];               // 800 KB
__device__ float  g_part2[KOUT * FS * BATCH];              // 80 KB

// ---------------------------------------------------------------------------
__device__ __forceinline__ __half2 u2h2(unsigned int u) {
    return *reinterpret_cast<__half2*>(&u);
}
__device__ __forceinline__ __half2 gate2(__half2 a, __half2 b,
                                         __half2 k0, __half2 k1,
                                         __half2 k2, __half2 k3) {
    __half2 t = __hfma2(k1, a, k0);
    t = __hfma2(k2, b, t);
    return __hfma2(k3, __hmul2(a, b), t);
}
__device__ __forceinline__ uint4 gate_u4(uint4 pc, uint4 av, uint4 bv) {
    __half2 k0 = u2h2(pc.x), k1 = u2h2(pc.y), k2 = u2h2(pc.z), k3 = u2h2(pc.w);
    uint4 r;
    ((__half2*)&r)[0] = gate2(((__half2*)&av)[0], ((__half2*)&bv)[0], k0, k1, k2, k3);
    ((__half2*)&r)[1] = gate2(((__half2*)&av)[1], ((__half2*)&bv)[1], k0, k1, k2, k3);
    ((__half2*)&r)[2] = gate2(((__half2*)&av)[2], ((__half2*)&bv)[2], k0, k1, k2, k3);
    ((__half2*)&r)[3] = gate2(((__half2*)&av)[3], ((__half2*)&bv)[3], k0, k1, k2, k3);
    return r;
}

// ---------------------------------------------------------------------------
// Coef block: 256 neurons, coalesced float4 loads staged through smem.
__device__ __forceinline__ void coef_block(const float* __restrict__ w,
                                           int dstOff, int blk) {
    __shared__ float sw[16][257];
    int n0 = blk * 256;
    const float4* wv = (const float4*)(w + (size_t)n0 * 16);
    #pragma unroll
    for (int it = 0; it < 4; it++) {
        int i = threadIdx.x + it * 256;          // 0..1023
        float4 f = __ldg(wv + i);
        int n = i >> 2;
        int j = (i & 3) * 4;
        sw[j + 0][n] = f.x;
        sw[j + 1][n] = f.y;
        sw[j + 2][n] = f.z;
        sw[j + 3][n] = f.w;
    }
    __syncthreads();

    int t = threadIdx.x;
    float v[16];
    float m = -1e30f;
    #pragma unroll
    for (int i = 0; i < 16; i++) { v[i] = sw[i][t]; m = fmaxf(m, v[i]); }
    float s = 0.f;
    #pragma unroll
    for (int i = 0; i < 16; i++) { v[i] = __expf(v[i] - m); s += v[i]; }
    float inv = __fdividef(1.0f, s);
    #pragma unroll
    for (int i = 0; i < 16; i++) v[i] *= inv;

    float c0 = v[8]+v[9]+v[10]+v[11]+v[12]+v[13]+v[14]+v[15];
    float c1 = v[2]+v[3]+v[6]+v[7] - v[8]-v[9]-v[12]-v[13];
    float c2 = v[4]+v[5]+v[6]+v[7] - v[8]-v[9]-v[10]-v[11];
    float c3 = v[1] - v[2] - v[4] - 2.f*v[6] - v[7]
             + v[8] + 2.f*v[9] + v[11] + v[13] - v[14];

    __half2 h0 = __half2half2(__float2half_rn(c0));
    __half2 h1 = __half2half2(__float2half_rn(c1));
    __half2 h2 = __half2half2(__float2half_rn(c2));
    __half2 h3 = __half2half2(__float2half_rn(c3));
    uint4 pk;
    pk.x = *reinterpret_cast<unsigned int*>(&h0);
    pk.y = *reinterpret_cast<unsigned int*>(&h1);
    pk.z = *reinterpret_cast<unsigned int*>(&h2);
    pk.w = *reinterpret_cast<unsigned int*>(&h3);
    g_coefh4[dstOff + n0 + t] = pk;
}

// ---------------------------------------------------------------------------
// Prologue: blocks [0,256) transpose x -> xT fp16; then CBLK layer-1 coef
// blocks (layer-2/3 coefs are co-scheduled with k_layer1).
__global__ __launch_bounds__(256)
void k_pre(const float* __restrict__ x, const float* __restrict__ w1) {
    if (blockIdx.x >= 256) {
        coef_block(w1, 0, blockIdx.x - 256);
        return;
    }
    __shared__ float tile[32][33];
    int d0 = (blockIdx.x & 31) * 32;
    int b0 = (blockIdx.x >> 5) * 32;
    int tx = threadIdx.x & 31;
    int ty = threadIdx.x >> 5;
    #pragma unroll
    for (int r = 0; r < 4; r++)
        tile[ty + r * 8][tx] =
            x[(size_t)(b0 + ty + r * 8) * IN_DIM + d0 + tx];
    __syncthreads();
    #pragma unroll
    for (int r = 0; r < 4; r++)
        g_xT[(size_t)(d0 + ty + r * 8) * BATCH + b0 + tx] =
            __float2half_rn(tile[tx][ty + r * 8]);
}

// ---------------------------------------------------------------------------
// Layer 1: xT -> bufA, TWO neurons per warp; co-schedules layer-2 AND
// layer-3 coef blocks (fills idle issue slots of latency-bound layer warps).
__global__ __launch_bounds__(256)
void k_layer1(const int* __restrict__ ia, const int* __restrict__ ib,
              const float* __restrict__ w2, const float* __restrict__ w3) {
    if (blockIdx.x >= WIDTH / 16) {
        int blk = blockIdx.x - WIDTH / 16;
        if (blk < CBLK) coef_block(w2, WIDTH, blk);
        else            coef_block(w3, 2 * WIDTH, blk - CBLK);
        return;
    }
    int warp = blockIdx.x * 8 + (threadIdx.x >> 5);
    int n0   = warp * 2;
    int n1   = n0 + 1;
    int lane = threadIdx.x & 31;

    const __half* src = g_xT;
    __half*       dst = g_bufA;

    int A0 = __ldg(ia + n0), B0 = __ldg(ib + n0);
    int A1 = __ldg(ia + n1), B1 = __ldg(ib + n1);
    uint4 pc0 = __ldg(&g_coefh4[n0]);
    uint4 pc1 = __ldg(&g_coefh4[n1]);

    uint4 a0 = __ldg((const uint4*)(src + (size_t)A0 * BATCH) + lane);
    uint4 b0 = __ldg((const uint4*)(src + (size_t)B0 * BATCH) + lane);
    uint4 a1 = __ldg((const uint4*)(src + (size_t)A1 * BATCH) + lane);
    uint4 b1 = __ldg((const uint4*)(src + (size_t)B1 * BATCH) + lane);

    ((uint4*)(dst + (size_t)n0 * BATCH))[lane] = gate_u4(pc0, a0, b0);
    ((uint4*)(dst + (size_t)n1 * BATCH))[lane] = gate_u4(pc1, a1, b1);
}

// ---------------------------------------------------------------------------
// Fused layer-2 + layer-3 + partial group sum. Chunks of 2 l3-neurons:
// batched warp-uniform index chase (ia3 -> ia2), then 8 independent uint4
// gathers from bufA, 4 inline l2 gates, 2 l3 gates, half2 accumulation.
__global__ __launch_bounds__(256)
void k_l23_reduce(const int* __restrict__ ia2, const int* __restrict__ ib2,
                  const int* __restrict__ ia3, const int* __restrict__ ib3) {
    int k    = blockIdx.x;            // 0..9
    int s    = blockIdx.y;            // 0..NS-1
    int w    = threadIdx.x >> 5;      // 0..7
    int lane = threadIdx.x & 31;

    const __half* src = g_bufA;       // layer-1 output
    int n0 = k * GROUP + s * JS + w * JW;

    __half2 acc[4];
    #pragma unroll
    for (int h = 0; h < 4; h++) acc[h] = __half2half2(__ushort_as_half(0));

    #pragma unroll 2
    for (int jj = 0; jj < JW / 2; jj++) {
        int nA = n0 + 2 * jj;
        int nB = nA + 1;
        int m0 = __ldg(ia3 + nA), m1 = __ldg(ib3 + nA);
        int m2 = __ldg(ia3 + nB), m3 = __ldg(ib3 + nB);
        uint4 cnA = __ldg(&g_coefh4[2 * WIDTH + nA]);
        uint4 cnB = __ldg(&g_coefh4[2 * WIDTH + nB]);
        int p0 = __ldg(ia2 + m0), p1 = __ldg(ib2 + m0);
        int p2 = __ldg(ia2 + m1), p3 = __ldg(ib2 + m1);
        int p4 = __ldg(ia2 + m2), p5 = __ldg(ib2 + m2);
        int p6 = __ldg(ia2 + m3), p7 = __ldg(ib2 + m3);
        uint4 cm0 = __ldg(&g_coefh4[WIDTH + m0]);
        uint4 cm1 = __ldg(&g_coefh4[WIDTH + m1]);
        uint4 cm2 = __ldg(&g_coefh4[WIDTH + m2]);
        uint4 cm3 = __ldg(&g_coefh4[WIDTH + m3]);
        uint4 g0 = __ldg((const uint4*)(src + (size_t)p0 * BATCH) + lane);
        uint4 g1 = __ldg((const uint4*)(src + (size_t)p1 * BATCH) + lane);
        uint4 g2 = __ldg((const uint4*)(src + (size_t)p2 * BATCH) + lane);
        uint4 g3 = __ldg((const uint4*)(src + (size_t)p3 * BATCH) + lane);
        uint4 g4 = __ldg((const uint4*)(src + (size_t)p4 * BATCH) + lane);
        uint4 g5 = __ldg((const uint4*)(src + (size_t)p5 * BATCH) + lane);
        uint4 g6 = __ldg((const uint4*)(src + (size_t)p6 * BATCH) + lane);
        uint4 g7 = __ldg((const uint4*)(src + (size_t)p7 * BATCH) + lane);

        uint4 l2a = gate_u4(cm0, g0, g1);
        uint4 l2b = gate_u4(cm1, g2, g3);
        uint4 l2c = gate_u4(cm2, g4, g5);
        uint4 l2d = gate_u4(cm3, g6, g7);

        __half2 kA0 = u2h2(cnA.x), kA1 = u2h2(cnA.y),
                kA2 = u2h2(cnA.z), kA3 = u2h2(cnA.w);
        __half2 kB0 = u2h2(cnB.x), kB1 = u2h2(cnB.y),
                kB2 = u2h2(cnB.z), kB3 = u2h2(cnB.w);
        #pragma unroll
        for (int h = 0; h < 4; h++) {
            acc[h] = __hadd2(acc[h],
                gate2(((__half2*)&l2a)[h], ((__half2*)&l2b)[h], kA0, kA1, kA2, kA3));
            acc[h] = __hadd2(acc[h],
                gate2(((__half2*)&l2c)[h], ((__half2*)&l2d)[h], kB0, kB1, kB2, kB3));
        }
    }

    __shared__ float part[L3WARPS][BATCH];
    #pragma unroll
    for (int h = 0; h < 4; h++) {
        float2 f = __half22float2(acc[h]);
        part[w][lane * 8 + 2 * h]     = f.x;
        part[w][lane * 8 + 2 * h + 1] = f.y;
    }
    __syncthreads();

    int col = threadIdx.x;
    float v = 0.f;
    #pragma unroll
    for (int i = 0; i < L3WARPS; i++) v += part[i][col];
    g_part[(size_t)(k * NS + s) * BATCH + col] = v;
}

// ---------------------------------------------------------------------------
// Final reduce, stage A: grid (KOUT, FS); block (k,f) sums NS/FS=10 splits
// for all 256 batch columns (coalesced). 80 blocks.
__global__ void k_freduceA() {
    int k = blockIdx.x;
    int f = blockIdx.y;
    int b = threadIdx.x;
    const float* base = g_part + ((size_t)k * NS + f * (NS / FS)) * BATCH + b;
    float acc = 0.f;
    #pragma unroll
    for (int s = 0; s < NS / FS; s++) acc += base[(size_t)s * BATCH];
    g_part2[((size_t)k * FS + f) * BATCH + b] = acc;
}

// Stage B: sum FS partials, scale by 1/TAU, write out[b][k]. 10 blocks.
__global__ void k_freduceB(float* __restrict__ out) {
    int k = blockIdx.x;
    int b = threadIdx.x;
    float acc = 0.f;
    #pragma unroll
    for (int f = 0; f < FS; f++)
        acc += g_part2[((size_t)k * FS + f) * BATCH + b];
    out[b * KOUT + k] = acc * (1.0f / 30.0f);
}

// ---------------------------------------------------------------------------
extern "C" void kernel_launch(void* const* d_in, const int* in_sizes, int n_in,
                              void* d_out, int out_size) {
    const float* x   = (const float*)d_in[0];
    const float* w1  = (const float*)d_in[1];
    const float* w2  = (const float*)d_in[2];
    const float* w3  = (const float*)d_in[3];
    const int*   ia1 = (const int*)d_in[4];
    const int*   ib1 = (const int*)d_in[5];
    const int*   ia2 = (const int*)d_in[6];
    const int*   ib2 = (const int*)d_in[7];
    const int*   ia3 = (const int*)d_in[8];
    const int*   ib3 = (const int*)d_in[9];
    float* out = (float*)d_out;

    // transpose + layer-1 coefs
    k_pre<<<256 + CBLK, 256>>>(x, w1);
    // layer 1 (+ layer-2/3 coefs co-scheduled)
    k_layer1<<<WIDTH / 16 + 2 * CBLK, 256>>>(ia1, ib1, w2, w3);
    // fused layer-2 + layer-3 + reduce
    k_l23_reduce<<<dim3(KOUT, NS), 256>>>(ia2, ib2, ia3, ib3);
    // two-stage final reduce (parallel, coalesced)
    k_freduceA<<<dim3(KOUT, FS), 256>>>();
    k_freduceB<<<KOUT, BATCH>>>(out);
}